// round 7
// baseline (speedup 1.0000x reference)
#include <cuda_runtime.h>

// Dilation1D: out[r] = max_{j=0..10} x[r-5+j] + h[j],  h[j] = -(j-5)^2/(4*scale)
// Symmetric-tap form: out[r] = max(x[r], max_{d=1..5} max(x[r-d],x[r+d]) + h_d)
//
// Warp-shuffle halo: each lane loads ONE aligned float4 (perfectly coalesced,
// 4 wavefronts/warp = structural L1tex minimum), halo +-5 comes from neighbor
// lanes via shfl. Only edge lanes (0,1,30,31) issue 2 extra predicated LDG.128.
// This kills the 5x L1 halo re-load amplification of the blocked-window scheme.

#define BLOCK 256   // 8 warps, 128 outputs/warp, 1024 outputs/block

__global__ __launch_bounds__(BLOCK) void dilate1d_kernel(
    const float* __restrict__ x,
    const float* __restrict__ scale_p,
    float* __restrict__ out,
    int n)
{
    const int lane   = threadIdx.x & 31;
    const int warpId = blockIdx.x * (BLOCK / 32) + (threadIdx.x >> 5);
    const int W      = warpId * 128;        // warp tile start
    const int g      = W + lane * 4;        // this lane's first output index

    if (W >= n) return;                     // warp-uniform exit (shfl-safe)

    const float s = __ldg(scale_p);
    const float c = -0.25f / s;
    const float h1 =  1.0f * c;
    const float h2 =  4.0f * c;
    const float h3 =  9.0f * c;
    const float h4 = 16.0f * c;
    const float h5 = 25.0f * c;
    const float NEG_INF = __int_as_float(0xff800000);

    // Window for outputs g..g+3:  x[g-5 .. g+8]
    float m5, m4, m3, m2, m1, c0, c1, c2, c3, p1, p2, p3, p4, p5;

    const bool interior = (W >= 8) && (W + 136 <= n);

    if (interior) {
        // Own chunk: one perfectly coalesced, aligned LDG.128 per lane.
        float4 v = *reinterpret_cast<const float4*>(x + g);

        // Edge halo loads (predicated; active lanes 0,1,30,31 -> ~6 wavefronts):
        //  lane 0:  eA = x[W-8..W-5]   eB = x[W-4..W-1]
        //  lane 1:  eA = x[W-4..W-1]
        //  lane 30: eA = x[W+128..131]
        //  lane 31: eA = x[W+132..135] eB = x[W+128..131]
        float4 eA, eB;
        if (lane < 2 || lane >= 30) {
            int off = (lane < 2) ? (-8 + 4 * lane) : (128 + 4 * (lane - 30));
            eA = *reinterpret_cast<const float4*>(x + W + off);
        }
        if (lane == 0 || lane == 31) {
            int off = (lane == 0) ? -4 : 128;
            eB = *reinterpret_cast<const float4*>(x + W + off);
        }

        const unsigned FULL = 0xffffffffu;
        float ux = __shfl_up_sync  (FULL, v.x, 1);   // x[g-4]
        float uy = __shfl_up_sync  (FULL, v.y, 1);   // x[g-3]
        float uz = __shfl_up_sync  (FULL, v.z, 1);   // x[g-2]
        float uw = __shfl_up_sync  (FULL, v.w, 1);   // x[g-1]
        float lw = __shfl_up_sync  (FULL, v.w, 2);   // x[g-5]
        float dx = __shfl_down_sync(FULL, v.x, 1);   // x[g+4]
        float dy = __shfl_down_sync(FULL, v.y, 1);   // x[g+5]
        float dz = __shfl_down_sync(FULL, v.z, 1);   // x[g+6]
        float dw = __shfl_down_sync(FULL, v.w, 1);   // x[g+7]
        float rx = __shfl_down_sync(FULL, v.x, 2);   // x[g+8]

        // Patch lanes whose shfl fell off the warp edge.
        if (lane == 0)  { ux = eB.x; uy = eB.y; uz = eB.z; uw = eB.w; lw = eA.w; }
        if (lane == 1)  { lw = eA.w; }
        if (lane == 30) { rx = eA.x; }
        if (lane == 31) { dx = eB.x; dy = eB.y; dz = eB.z; dw = eB.w; rx = eA.x; }

        m5 = lw; m4 = ux; m3 = uy; m2 = uz; m1 = uw;
        c0 = v.x; c1 = v.y; c2 = v.z; c3 = v.w;
        p1 = dx; p2 = dy; p3 = dz; p4 = dw; p5 = rx;
    } else {
        // Boundary warp (first/last only): guarded scalar window, -inf pad.
        float w[14];
        #pragma unroll
        for (int k = 0; k < 14; k++) {
            int idx = g - 5 + k;
            w[k] = (idx >= 0 && idx < n) ? x[idx] : NEG_INF;
        }
        m5 = w[0];  m4 = w[1];  m3 = w[2];  m2 = w[3];  m1 = w[4];
        c0 = w[5];  c1 = w[6];  c2 = w[7];  c3 = w[8];
        p1 = w[9];  p2 = w[10]; p3 = w[11]; p4 = w[12]; p5 = w[13];
    }

    float o0 = c0;
    o0 = fmaxf(o0, fmaxf(m1, c1) + h1);
    o0 = fmaxf(o0, fmaxf(m2, c2) + h2);
    o0 = fmaxf(o0, fmaxf(m3, c3) + h3);
    o0 = fmaxf(o0, fmaxf(m4, p1) + h4);
    o0 = fmaxf(o0, fmaxf(m5, p2) + h5);

    float o1 = c1;
    o1 = fmaxf(o1, fmaxf(c0, c2) + h1);
    o1 = fmaxf(o1, fmaxf(m1, c3) + h2);
    o1 = fmaxf(o1, fmaxf(m2, p1) + h3);
    o1 = fmaxf(o1, fmaxf(m3, p2) + h4);
    o1 = fmaxf(o1, fmaxf(m4, p3) + h5);

    float o2 = c2;
    o2 = fmaxf(o2, fmaxf(c1, c3) + h1);
    o2 = fmaxf(o2, fmaxf(c0, p1) + h2);
    o2 = fmaxf(o2, fmaxf(m1, p2) + h3);
    o2 = fmaxf(o2, fmaxf(m2, p3) + h4);
    o2 = fmaxf(o2, fmaxf(m3, p4) + h5);

    float o3 = c3;
    o3 = fmaxf(o3, fmaxf(c2, p1) + h1);
    o3 = fmaxf(o3, fmaxf(c1, p2) + h2);
    o3 = fmaxf(o3, fmaxf(c0, p3) + h3);
    o3 = fmaxf(o3, fmaxf(m1, p4) + h4);
    o3 = fmaxf(o3, fmaxf(m2, p5) + h5);

    if (interior || g + 4 <= n) {
        __stcs(reinterpret_cast<float4*>(out + g), make_float4(o0, o1, o2, o3));
    } else {
        if (g + 0 < n) out[g + 0] = o0;
        if (g + 1 < n) out[g + 1] = o1;
        if (g + 2 < n) out[g + 2] = o2;
        if (g + 3 < n) out[g + 3] = o3;
    }
}

extern "C" void kernel_launch(void* const* d_in, const int* in_sizes, int n_in,
                              void* d_out, int out_size)
{
    const float* x       = (const float*)d_in[0];
    const float* scale_p = (const float*)d_in[1];
    float*       out     = (float*)d_out;
    int n = in_sizes[0];

    int outputsPerBlock = (BLOCK / 32) * 128;   // 1024
    int blocks = (n + outputsPerBlock - 1) / outputsPerBlock;
    dilate1d_kernel<<<blocks, BLOCK>>>(x, scale_p, out, n);
}